// round 4
// baseline (speedup 1.0000x reference)
#include <cuda_runtime.h>
#include <cuda_bf16.h>
#include <math.h>
#include <stdint.h>

// ---------------------------------------------------------------------------
// Problem constants
// ---------------------------------------------------------------------------
#define BATCH 2
#define SEQ   2048
#define DIM   2048
#define NHEAD 32
#define DHEAD 64
#define FFN   8192
#define LDWIN 18560              // W_in row stride (full)
#define HCOLS 10368              // used cols of W_in: q|k|v|ffn
#define OUTK  10240              // concat dim: attn(2048)+ffn(8192)
#define MTOK  (BATCH*SEQ)
#define LN_EPS 1e-5f
#define QSCALE 0.125f
#define LOG2E  1.4426950408889634f

// ---------------------------------------------------------------------------
// Scratch (device globals)
// ---------------------------------------------------------------------------
__device__ float g_xn[(size_t)MTOK * DIM];      // LN output (residual)
__device__ float g_h[(size_t)MTOK * HCOLS];     // GEMM1 output fp32
__device__ __nv_bfloat16 g_a1hi[(size_t)MTOK * DIM];
__device__ __nv_bfloat16 g_a1lo[(size_t)MTOK * DIM];
__device__ __nv_bfloat16 g_w1hi[(size_t)HCOLS * DIM];   // W_in^T split [10368,2048]
__device__ __nv_bfloat16 g_w1lo[(size_t)HCOLS * DIM];
__device__ __nv_bfloat16 g_a2hi[(size_t)MTOK * OUTK];   // concat split [4096,10240]
__device__ __nv_bfloat16 g_a2lo[(size_t)MTOK * OUTK];
__device__ __nv_bfloat16 g_w2hi[(size_t)DIM * OUTK];    // W_out^T split [2048,10240]
__device__ __nv_bfloat16 g_w2lo[(size_t)DIM * OUTK];

// ---------------------------------------------------------------------------
// PTX helpers (sm_80-era: cp.async + ldmatrix + mma.sync — legal on compute_103)
// ---------------------------------------------------------------------------
__device__ __forceinline__ uint32_t smem_u32(const void* p) {
    uint32_t a;
    asm("{ .reg .u64 t; cvta.to.shared.u64 t, %1; cvt.u32.u64 %0, t; }" : "=r"(a) : "l"(p));
    return a;
}
#define CP_ASYNC16(sa, gp) \
    asm volatile("cp.async.cg.shared.global [%0], [%1], 16;" :: "r"(sa), "l"(gp))
#define CP_COMMIT() asm volatile("cp.async.commit_group;" ::: "memory")
#define CP_WAIT(n)  asm volatile("cp.async.wait_group %0;" :: "n"(n) : "memory")

#define LDSM_X4(r0, r1, r2, r3, addr) \
    asm volatile("ldmatrix.sync.aligned.m8n8.x4.shared.b16 {%0,%1,%2,%3}, [%4];" \
        : "=r"(r0), "=r"(r1), "=r"(r2), "=r"(r3) : "r"(addr))

#define MMA16816(d, a0, a1, a2, a3, b0, b1) \
    asm volatile("mma.sync.aligned.m16n8k16.row.col.f32.bf16.bf16.f32 " \
        "{%0,%1,%2,%3}, {%4,%5,%6,%7}, {%8,%9}, {%0,%1,%2,%3};" \
        : "+f"((d)[0]), "+f"((d)[1]), "+f"((d)[2]), "+f"((d)[3]) \
        : "r"(a0), "r"(a1), "r"(a2), "r"(a3), "r"(b0), "r"(b1))

__device__ __forceinline__ __nv_bfloat162 bf2hi(float x, float y) {
    return __halves2bfloat162(__float2bfloat16(x), __float2bfloat16(y));
}
__device__ __forceinline__ __nv_bfloat162 bf2lo(float x, float y) {
    float rx = x - __bfloat162float(__float2bfloat16(x));
    float ry = y - __bfloat162float(__float2bfloat16(y));
    return __halves2bfloat162(__float2bfloat16(rx), __float2bfloat16(ry));
}

// Fast 2^t via FMA polynomial (no MUFU). Valid for t <= 0 (softmax domain).
__device__ __forceinline__ float exp2_poly(float t) {
    t = fmaxf(t, -60.0f);
    float fi = floorf(t);
    float f = t - fi;                 // [0,1)
    float p = 1.3333558e-3f;
    p = fmaf(p, f, 9.6181291e-3f);
    p = fmaf(p, f, 5.5504109e-2f);
    p = fmaf(p, f, 2.4022651e-1f);
    p = fmaf(p, f, 6.9314718e-1f);
    p = fmaf(p, f, 1.0f);
    float s = __int_as_float(((int)fi + 127) << 23);
    return s * p;
}

// ---------------------------------------------------------------------------
// Kernel 1: LayerNorm + bf16 split of output (A1 for GEMM1)
// ---------------------------------------------------------------------------
__global__ void ln_split_kernel(const float* __restrict__ x,
                                const float* __restrict__ gamma,
                                const float* __restrict__ beta,
                                float* __restrict__ xn,
                                __nv_bfloat16* __restrict__ ahi,
                                __nv_bfloat16* __restrict__ alo) {
    int row = blockIdx.x;
    int tid = threadIdx.x;
    const float4* xr = reinterpret_cast<const float4*>(x + (size_t)row * DIM);
    float4 a = xr[tid];
    float4 b = xr[tid + 256];
    float s  = a.x + a.y + a.z + a.w + b.x + b.y + b.z + b.w;
    float s2 = a.x*a.x + a.y*a.y + a.z*a.z + a.w*a.w
             + b.x*b.x + b.y*b.y + b.z*b.z + b.w*b.w;
    #pragma unroll
    for (int off = 16; off > 0; off >>= 1) {
        s  += __shfl_xor_sync(0xffffffffu, s,  off);
        s2 += __shfl_xor_sync(0xffffffffu, s2, off);
    }
    __shared__ float ss[8], ss2[8];
    int wid = tid >> 5, lane = tid & 31;
    if (lane == 0) { ss[wid] = s; ss2[wid] = s2; }
    __syncthreads();
    s  = ss[0] + ss[1] + ss[2] + ss[3] + ss[4] + ss[5] + ss[6] + ss[7];
    s2 = ss2[0]+ ss2[1]+ ss2[2]+ ss2[3]+ ss2[4]+ ss2[5]+ ss2[6]+ ss2[7];
    float mean = s * (1.0f / DIM);
    float var  = s2 * (1.0f / DIM) - mean * mean;
    float rstd = rsqrtf(var + LN_EPS);

    const float4* g4 = reinterpret_cast<const float4*>(gamma);
    const float4* b4 = reinterpret_cast<const float4*>(beta);
    float4 g0 = g4[tid], g1 = g4[tid + 256];
    float4 be0 = b4[tid], be1 = b4[tid + 256];
    float4 o0, o1;
    o0.x = (a.x - mean) * rstd * g0.x + be0.x;
    o0.y = (a.y - mean) * rstd * g0.y + be0.y;
    o0.z = (a.z - mean) * rstd * g0.z + be0.z;
    o0.w = (a.w - mean) * rstd * g0.w + be0.w;
    o1.x = (b.x - mean) * rstd * g1.x + be1.x;
    o1.y = (b.y - mean) * rstd * g1.y + be1.y;
    o1.z = (b.z - mean) * rstd * g1.z + be1.z;
    o1.w = (b.w - mean) * rstd * g1.w + be1.w;
    float4* o4 = reinterpret_cast<float4*>(xn + (size_t)row * DIM);
    o4[tid] = o0;
    o4[tid + 256] = o1;

    __nv_bfloat162* ph = reinterpret_cast<__nv_bfloat162*>(ahi + (size_t)row * DIM);
    __nv_bfloat162* pl = reinterpret_cast<__nv_bfloat162*>(alo + (size_t)row * DIM);
    ph[tid*2+0]   = bf2hi(o0.x, o0.y);  pl[tid*2+0]   = bf2lo(o0.x, o0.y);
    ph[tid*2+1]   = bf2hi(o0.z, o0.w);  pl[tid*2+1]   = bf2lo(o0.z, o0.w);
    ph[tid*2+512] = bf2hi(o1.x, o1.y);  pl[tid*2+512] = bf2lo(o1.x, o1.y);
    ph[tid*2+513] = bf2hi(o1.z, o1.w);  pl[tid*2+513] = bf2lo(o1.z, o1.w);
}

// ---------------------------------------------------------------------------
// Kernel 2: transpose + bf16 split of weight matrices.
// ---------------------------------------------------------------------------
__global__ void tsplit_kernel(const float* __restrict__ src, int ld_src,
                              __nv_bfloat16* __restrict__ dhi,
                              __nv_bfloat16* __restrict__ dlo, int ld_dst) {
    __shared__ float t[32][33];
    int n0 = blockIdx.x * 32, k0 = blockIdx.y * 32;
    int tx = threadIdx.x, ty = threadIdx.y;
    #pragma unroll
    for (int i = 0; i < 4; i++)
        t[ty + 8*i][tx] = src[(size_t)(k0 + ty + 8*i) * ld_src + n0 + tx];
    __syncthreads();
    #pragma unroll
    for (int i = 0; i < 4; i++) {
        float v = t[tx][ty + 8*i];
        size_t o = (size_t)(n0 + ty + 8*i) * ld_dst + k0 + tx;
        __nv_bfloat16 h = __float2bfloat16(v);
        dhi[o] = h;
        dlo[o] = __float2bfloat16(v - __bfloat162float(h));
    }
}

// ---------------------------------------------------------------------------
// Tensor-core GEMM (mma.sync bf16, 3-term hi/lo split).
// C[M,N] = (Ahi+Alo)[M,K] @ (Bhi+Blo)^T ([N,K] K-major), fp32 accum.
// CTA tile 128x128, K-chunk 32, 3-stage cp.async pipeline, 256 threads.
// Each fragment loaded from SMEM exactly ONCE per chunk; A fragments stay
// register-resident across all 3 split passes.
// ---------------------------------------------------------------------------
#define BK     32
#define SROWB  80            // bytes per smem row (32 bf16 + 4 pad)
#define OFF_ALO 10240
#define OFF_BHI 20480
#define OFF_BLO 30720
#define STAGEB  40960
#define NSTAGE  3

template <bool RES>
__global__ __launch_bounds__(256, 1) void gemm_mma(
        const __nv_bfloat16* __restrict__ Ahi, const __nv_bfloat16* __restrict__ Alo,
        const __nv_bfloat16* __restrict__ Bhi, const __nv_bfloat16* __restrict__ Blo,
        float* __restrict__ C, int K, int ldc, const float* __restrict__ resid) {
    extern __shared__ __align__(16) char dsm[];
    uint32_t sbase = smem_u32(dsm);

    int tid  = threadIdx.x;
    int wid  = tid >> 5;
    int lane = tid & 31;
    int wm   = wid & 3;          // M quarter (32 rows)
    int wn   = wid >> 2;         // N half   (64 cols)

    int m0 = blockIdx.x * 128;   // grid.x = M tiles -> wave shares B tiles
    int n0 = blockIdx.y * 128;

    // cp.async per-thread mapping: 512 16B-chunks per (sub)tile, 2 per thread
    uint32_t sO[2]; size_t gO[2];
    #pragma unroll
    for (int i = 0; i < 2; i++) {
        int idx = tid + i * 256;
        int row = idx >> 2, c = idx & 3;
        sO[i] = (uint32_t)(row * SROWB + c * 16);
        gO[i] = (size_t)row * K + c * 8;
    }
    const __nv_bfloat16* gAhi = Ahi + (size_t)m0 * K;
    const __nv_bfloat16* gAlo = Alo + (size_t)m0 * K;
    const __nv_bfloat16* gBhi = Bhi + (size_t)n0 * K;
    const __nv_bfloat16* gBlo = Blo + (size_t)n0 * K;

    const int NC = K / BK;

    auto load_chunk = [&](int c) {
        uint32_t base = sbase + (uint32_t)(c % NSTAGE) * STAGEB;
        size_t co = (size_t)c * BK;
        #pragma unroll
        for (int i = 0; i < 2; i++) {
            CP_ASYNC16(base + sO[i],           (const void*)(gAhi + gO[i] + co));
            CP_ASYNC16(base + OFF_ALO + sO[i], (const void*)(gAlo + gO[i] + co));
            CP_ASYNC16(base + OFF_BHI + sO[i], (const void*)(gBhi + gO[i] + co));
            CP_ASYNC16(base + OFF_BLO + sO[i], (const void*)(gBlo + gO[i] + co));
        }
    };

    float acc[2][8][4];
    #pragma unroll
    for (int i = 0; i < 2; i++)
        #pragma unroll
        for (int j = 0; j < 8; j++)
            #pragma unroll
            for (int v = 0; v < 4; v++) acc[i][j][v] = 0.0f;

    // prologue: fill pipeline
    #pragma unroll
    for (int c = 0; c < NSTAGE - 1; c++) { load_chunk(c); CP_COMMIT(); }

    uint32_t aBase = (uint32_t)((wm * 32 + (lane & 15)) * SROWB + (lane >> 4) * 16);
    uint32_t bBase = (uint32_t)((wn * 64 + (lane & 15)) * SROWB + (lane >> 4) * 16);

    for (int c = 0; c < NC; c++) {
        CP_WAIT(NSTAGE - 2);
        __syncthreads();
        if (c + NSTAGE - 1 < NC) load_chunk(c + NSTAGE - 1);
        CP_COMMIT();

        uint32_t buf = sbase + (uint32_t)(c % NSTAGE) * STAGEB;

        // A fragments (hi + lo), loaded once, live across all passes.
        uint32_t aH[2][2][4], aL[2][2][4];
        #pragma unroll
        for (int mt = 0; mt < 2; mt++) {
            #pragma unroll
            for (int ks = 0; ks < 2; ks++) {
                uint32_t ad = buf + aBase + mt * (16 * SROWB) + ks * 32;
                LDSM_X4(aH[mt][ks][0], aH[mt][ks][1], aH[mt][ks][2], aH[mt][ks][3], ad);
                LDSM_X4(aL[mt][ks][0], aL[mt][ks][1], aL[mt][ks][2], aL[mt][ks][3], ad + OFF_ALO);
            }
        }
        // B fragments per 16-col group, each loaded once; 12 MMAs per (g, ks).
        #pragma unroll
        for (int g = 0; g < 4; g++) {
            #pragma unroll
            for (int ks = 0; ks < 2; ks++) {
                uint32_t bd = buf + bBase + g * (16 * SROWB) + ks * 32;
                uint32_t bh[4], bl[4];
                LDSM_X4(bh[0], bh[1], bh[2], bh[3], bd + OFF_BHI);
                LDSM_X4(bl[0], bl[1], bl[2], bl[3], bd + OFF_BLO);
                int nt0 = 2 * g, nt1 = 2 * g + 1;
                // hi * hi
                MMA16816(acc[0][nt0], aH[0][ks][0], aH[0][ks][1], aH[0][ks][2], aH[0][ks][3], bh[0], bh[2]);
                MMA16816(acc[0][nt1], aH[0][ks][0], aH[0][ks][1], aH[0][ks][2], aH[0][ks][3], bh[1], bh[3]);
                MMA16816(acc[1][nt0], aH[1][ks][0], aH[1][ks][1], aH[1][ks][2], aH[1][ks][3], bh[0], bh[2]);
                MMA16816(acc[1][nt1], aH[1][ks][0], aH[1][ks][1], aH[1][ks][2], aH[1][ks][3], bh[1], bh[3]);
                // hi * lo
                MMA16816(acc[0][nt0], aH[0][ks][0], aH[0][ks][1], aH[0][ks][2], aH[0][ks][3], bl[0], bl[2]);
                MMA16816(acc[0][nt1], aH[0][ks][0], aH[0][ks][1], aH[0][ks][2], aH[0][ks][3], bl[1], bl[3]);
                MMA16816(acc[1][nt0], aH[1][ks][0], aH[1][ks][1], aH[1][ks][2], aH[1][ks][3], bl[0], bl[2]);
                MMA16816(acc[1][nt1], aH[1][ks][0], aH[1][ks][1], aH[1][ks][2], aH[1][ks][3], bl[1], bl[3]);
                // lo * hi
                MMA16816(acc[0][nt0], aL[0][ks][0], aL[0][ks][1], aL[0][ks][2], aL[0][ks][3], bh[0], bh[2]);
                MMA16816(acc[0][nt1], aL[0][ks][0], aL[0][ks][1], aL[0][ks][2], aL[0][ks][3], bh[1], bh[3]);
                MMA16816(acc[1][nt0], aL[1][ks][0], aL[1][ks][1], aL[1][ks][2], aL[1][ks][3], bh[0], bh[2]);
                MMA16816(acc[1][nt1], aL[1][ks][0], aL[1][ks][1], aL[1][ks][2], aL[1][ks][3], bh[1], bh[3]);
            }
        }
    }

    // Epilogue
    int g = lane >> 2, q = lane & 3;
    #pragma unroll
    for (int mt = 0; mt < 2; mt++) {
        #pragma unroll
        for (int nt = 0; nt < 8; nt++) {
            int rowm = m0 + wm * 32 + mt * 16 + g;
            int coln = n0 + wn * 64 + nt * 8 + q * 2;
            float* p0 = C + (size_t)rowm * ldc + coln;
            float* p1 = C + (size_t)(rowm + 8) * ldc + coln;
            float2 v0 = make_float2(acc[mt][nt][0], acc[mt][nt][1]);
            float2 v1 = make_float2(acc[mt][nt][2], acc[mt][nt][3]);
            if (RES) {
                const float2 r0 = *reinterpret_cast<const float2*>(resid + (size_t)rowm * ldc + coln);
                const float2 r1 = *reinterpret_cast<const float2*>(resid + (size_t)(rowm + 8) * ldc + coln);
                v0.x += r0.x; v0.y += r0.y;
                v1.x += r1.x; v1.y += r1.y;
            }
            *reinterpret_cast<float2*>(p0) = v0;
            *reinterpret_cast<float2*>(p1) = v1;
        }
    }
}

// ---------------------------------------------------------------------------
// Kernel: rotary (in-place on q & k regions of g_h).
// q additionally scaled by QSCALE * log2(e) so softmax works in log2 domain.
// ---------------------------------------------------------------------------
__global__ void rotary_kernel(float* __restrict__ h) {
    int row = blockIdx.x;
    int s = row & (SEQ - 1);
    float* hp = h + (size_t)row * HCOLS;
    for (int job = threadIdx.x; job < 1056; job += blockDim.x) {
        int c, base;
        float scl;
        if (job < 1024) { int hd = job >> 5; c = job & 31; base = hd * 64; scl = QSCALE * LOG2E; }
        else            { c = job - 1024; base = NHEAD * DHEAD; scl = 1.0f; }
        float inv = powf(10000.0f, -(float)c * (1.0f / 32.0f));
        float ang = (float)s * inv;
        float sn, cs;
        sincosf(ang, &sn, &cs);
        float qa = hp[base + c];
        float qb = hp[base + c + 32];
        hp[base + c]      = (qa * cs - qb * sn) * scl;
        hp[base + c + 32] = (qb * cs + qa * sn) * scl;
    }
}

// ---------------------------------------------------------------------------
// Kernel: causal MQA flash attention (log2-domain softmax, poly exp2).
// ---------------------------------------------------------------------------
__global__ __launch_bounds__(128) void attn_kernel(
        const float* __restrict__ h,
        __nv_bfloat16* __restrict__ a2hi, __nv_bfloat16* __restrict__ a2lo) {
    __shared__ float4 ks4[64][16];
    __shared__ float4 vs4[64][16];
    int tid  = threadIdx.x;
    int r    = blockIdx.x * 128 + tid;
    int head = blockIdx.y;
    int b    = blockIdx.z;

    const float* qp = h + (size_t)(b * SEQ + r) * HCOLS + head * DHEAD;
    float4 q4[16];
    #pragma unroll
    for (int i = 0; i < 16; i++) q4[i] = reinterpret_cast<const float4*>(qp)[i];

    float4 acc[16];
    #pragma unroll
    for (int i = 0; i < 16; i++) acc[i] = make_float4(0.f, 0.f, 0.f, 0.f);
    float mrow = -INFINITY, lsum = 0.0f;

    int ntile = 2 * (blockIdx.x + 1);
    for (int t = 0; t < ntile; t++) {
        int j0 = t * 64;
        __syncthreads();
        #pragma unroll
        for (int it = 0; it < 8; it++) {
            int idx = tid + it * 128;
            int jr = idx >> 4, d4 = idx & 15;
            const float* kp = h + (size_t)(b * SEQ + j0 + jr) * HCOLS + NHEAD * DHEAD;
            ks4[jr][d4] = reinterpret_cast<const float4*>(kp)[d4];
            vs4[jr][d4] = reinterpret_cast<const float4*>(kp + DHEAD)[d4];
        }
        __syncthreads();
        int jend = r - j0 + 1;
        if (jend > 64) jend = 64;
        for (int j = 0; j < jend; j++) {
            float dot = 0.0f;
            #pragma unroll
            for (int i = 0; i < 16; i++) {
                float4 kv = ks4[j][i];
                dot += q4[i].x * kv.x + q4[i].y * kv.y + q4[i].z * kv.z + q4[i].w * kv.w;
            }
            if (dot <= mrow) {
                float p = exp2_poly(dot - mrow);
                lsum += p;
                #pragma unroll
                for (int i = 0; i < 16; i++) {
                    float4 vv = vs4[j][i];
                    acc[i].x += p * vv.x; acc[i].y += p * vv.y;
                    acc[i].z += p * vv.z; acc[i].w += p * vv.w;
                }
            } else {
                float sc = exp2_poly(mrow - dot);
                mrow = dot;
                lsum = lsum * sc + 1.0f;
                #pragma unroll
                for (int i = 0; i < 16; i++) {
                    float4 vv = vs4[j][i];
                    acc[i].x = acc[i].x * sc + vv.x; acc[i].y = acc[i].y * sc + vv.y;
                    acc[i].z = acc[i].z * sc + vv.z; acc[i].w = acc[i].w * sc + vv.w;
                }
            }
        }
    }
    float inv = 1.0f / lsum;
    size_t ob = (size_t)(b * SEQ + r) * OUTK + head * DHEAD;
    __nv_bfloat162* ph = reinterpret_cast<__nv_bfloat162*>(a2hi + ob);
    __nv_bfloat162* pl = reinterpret_cast<__nv_bfloat162*>(a2lo + ob);
    #pragma unroll
    for (int i = 0; i < 16; i++) {
        float4 o = acc[i];
        o.x *= inv; o.y *= inv; o.z *= inv; o.w *= inv;
        ph[i*2+0] = bf2hi(o.x, o.y);  pl[i*2+0] = bf2lo(o.x, o.y);
        ph[i*2+1] = bf2hi(o.z, o.w);  pl[i*2+1] = bf2lo(o.z, o.w);
    }
}

// ---------------------------------------------------------------------------
// Kernel: split ffn region of g_h into A2 cols [2048, 10240)
// ---------------------------------------------------------------------------
__global__ void ffn_split_kernel(const float* __restrict__ h,
                                 __nv_bfloat16* __restrict__ a2hi,
                                 __nv_bfloat16* __restrict__ a2lo) {
    size_t i = (size_t)blockIdx.x * blockDim.x + threadIdx.x;
    int m  = (int)(i >> 11);
    int j4 = (int)(i & 2047);
    float4 v = *reinterpret_cast<const float4*>(h + (size_t)m * HCOLS + 2176 + j4 * 4);
    size_t ob = (size_t)m * OUTK + 2048 + j4 * 4;
    __nv_bfloat162* ph = reinterpret_cast<__nv_bfloat162*>(a2hi + ob);
    __nv_bfloat162* pl = reinterpret_cast<__nv_bfloat162*>(a2lo + ob);
    ph[0] = bf2hi(v.x, v.y);  pl[0] = bf2lo(v.x, v.y);
    ph[1] = bf2hi(v.z, v.w);  pl[1] = bf2lo(v.z, v.w);
}

// ---------------------------------------------------------------------------
extern "C" void kernel_launch(void* const* d_in, const int* in_sizes, int n_in,
                              void* d_out, int out_size) {
    const float* x     = (const float*)d_in[0];
    const float* W_in  = (const float*)d_in[1];
    const float* W_out = (const float*)d_in[2];
    const float* gamma = (const float*)d_in[3];
    const float* beta  = (const float*)d_in[4];
    float* out = (float*)d_out;

    float* xn;  cudaGetSymbolAddress((void**)&xn,  g_xn);
    float* h;   cudaGetSymbolAddress((void**)&h,   g_h);
    __nv_bfloat16 *a1hi, *a1lo, *w1hi, *w1lo, *a2hi, *a2lo, *w2hi, *w2lo;
    cudaGetSymbolAddress((void**)&a1hi, g_a1hi);
    cudaGetSymbolAddress((void**)&a1lo, g_a1lo);
    cudaGetSymbolAddress((void**)&w1hi, g_w1hi);
    cudaGetSymbolAddress((void**)&w1lo, g_w1lo);
    cudaGetSymbolAddress((void**)&a2hi, g_a2hi);
    cudaGetSymbolAddress((void**)&a2lo, g_a2lo);
    cudaGetSymbolAddress((void**)&w2hi, g_w2hi);
    cudaGetSymbolAddress((void**)&w2lo, g_w2lo);

    const int SMEM = NSTAGE * STAGEB;   // 122880
    cudaFuncSetAttribute(gemm_mma<false>, cudaFuncAttributeMaxDynamicSharedMemorySize, SMEM);
    cudaFuncSetAttribute(gemm_mma<true>,  cudaFuncAttributeMaxDynamicSharedMemorySize, SMEM);

    ln_split_kernel<<<MTOK, 256>>>(x, gamma, beta, xn, a1hi, a1lo);
    tsplit_kernel<<<dim3(HCOLS/32, DIM/32), dim3(32, 8)>>>(W_in, LDWIN, w1hi, w1lo, DIM);
    tsplit_kernel<<<dim3(DIM/32, OUTK/32), dim3(32, 8)>>>(W_out, DIM, w2hi, w2lo, OUTK);
    gemm_mma<false><<<dim3(MTOK/128, HCOLS/128), 256, SMEM>>>(
        a1hi, a1lo, w1hi, w1lo, h, DIM, HCOLS, nullptr);
    rotary_kernel<<<MTOK, 128>>>(h);
    attn_kernel<<<dim3(SEQ/128, NHEAD, BATCH), 128>>>(h, a2hi, a2lo);
    ffn_split_kernel<<<(MTOK * 2048) / 256, 256>>>(h, a2hi, a2lo);
    gemm_mma<true><<<dim3(MTOK/128, DIM/128), 256, SMEM>>>(
        a2hi, a2lo, w2hi, w2lo, out, OUTK, DIM, xn);
}

// round 5
// speedup vs baseline: 1.0609x; 1.0609x over previous
#include <cuda_runtime.h>
#include <cuda_bf16.h>
#include <math.h>
#include <stdint.h>

// ---------------------------------------------------------------------------
// Problem constants
// ---------------------------------------------------------------------------
#define BATCH 2
#define SEQ   2048
#define DIM   2048
#define NHEAD 32
#define DHEAD 64
#define FFN   8192
#define LDWIN 18560              // W_in row stride (full)
#define HCOLS 10368              // used cols of W_in: q|k|v|ffn
#define OUTK  10240              // concat dim: attn(2048)+ffn(8192)
#define MTOK  (BATCH*SEQ)
#define LN_EPS 1e-5f
#define QSCALE 0.125f
#define LOG2E  1.4426950408889634f

// ---------------------------------------------------------------------------
// Scratch (device globals)
// ---------------------------------------------------------------------------
__device__ float g_xn[(size_t)MTOK * DIM];      // LN output (residual)
__device__ float g_h[(size_t)MTOK * HCOLS];     // GEMM1 output fp32
__device__ __nv_bfloat16 g_a1hi[(size_t)MTOK * DIM];
__device__ __nv_bfloat16 g_a1lo[(size_t)MTOK * DIM];
__device__ __nv_bfloat16 g_w1hi[(size_t)HCOLS * DIM];   // W_in^T split [10368,2048]
__device__ __nv_bfloat16 g_w1lo[(size_t)HCOLS * DIM];
__device__ __nv_bfloat16 g_a2hi[(size_t)MTOK * OUTK];   // concat split [4096,10240]
__device__ __nv_bfloat16 g_a2lo[(size_t)MTOK * OUTK];
__device__ __nv_bfloat16 g_w2hi[(size_t)DIM * OUTK];    // W_out^T split [2048,10240]
__device__ __nv_bfloat16 g_w2lo[(size_t)DIM * OUTK];

// ---------------------------------------------------------------------------
// PTX helpers (sm_80-era: cp.async + ldmatrix + mma.sync — legal on compute_103)
// ---------------------------------------------------------------------------
__device__ __forceinline__ uint32_t smem_u32(const void* p) {
    uint32_t a;
    asm("{ .reg .u64 t; cvta.to.shared.u64 t, %1; cvt.u32.u64 %0, t; }" : "=r"(a) : "l"(p));
    return a;
}
#define CP_ASYNC16(sa, gp) \
    asm volatile("cp.async.cg.shared.global [%0], [%1], 16;" :: "r"(sa), "l"(gp))
#define CP_COMMIT() asm volatile("cp.async.commit_group;" ::: "memory")
#define CP_WAIT(n)  asm volatile("cp.async.wait_group %0;" :: "n"(n) : "memory")

#define LDSM_X4(r0, r1, r2, r3, addr) \
    asm volatile("ldmatrix.sync.aligned.m8n8.x4.shared.b16 {%0,%1,%2,%3}, [%4];" \
        : "=r"(r0), "=r"(r1), "=r"(r2), "=r"(r3) : "r"(addr))

#define MMA16816(d, a0, a1, a2, a3, b0, b1) \
    asm volatile("mma.sync.aligned.m16n8k16.row.col.f32.bf16.bf16.f32 " \
        "{%0,%1,%2,%3}, {%4,%5,%6,%7}, {%8,%9}, {%0,%1,%2,%3};" \
        : "+f"((d)[0]), "+f"((d)[1]), "+f"((d)[2]), "+f"((d)[3]) \
        : "r"(a0), "r"(a1), "r"(a2), "r"(a3), "r"(b0), "r"(b1))

__device__ __forceinline__ __nv_bfloat162 bf2hi(float x, float y) {
    return __halves2bfloat162(__float2bfloat16(x), __float2bfloat16(y));
}
__device__ __forceinline__ __nv_bfloat162 bf2lo(float x, float y) {
    float rx = x - __bfloat162float(__float2bfloat16(x));
    float ry = y - __bfloat162float(__float2bfloat16(y));
    return __halves2bfloat162(__float2bfloat16(rx), __float2bfloat16(ry));
}

// Fast 2^t via FMA polynomial (no MUFU). Valid for t <= 0 (softmax domain).
__device__ __forceinline__ float exp2_poly(float t) {
    t = fmaxf(t, -60.0f);
    float fi = floorf(t);
    float f = t - fi;                 // [0,1)
    float p = 1.3333558e-3f;
    p = fmaf(p, f, 9.6181291e-3f);
    p = fmaf(p, f, 5.5504109e-2f);
    p = fmaf(p, f, 2.4022651e-1f);
    p = fmaf(p, f, 6.9314718e-1f);
    p = fmaf(p, f, 1.0f);
    float s = __int_as_float(((int)fi + 127) << 23);
    return s * p;
}

// ---------------------------------------------------------------------------
// Kernel 1: LayerNorm + bf16 split of output (A1 for GEMM1)
// ---------------------------------------------------------------------------
__global__ void ln_split_kernel(const float* __restrict__ x,
                                const float* __restrict__ gamma,
                                const float* __restrict__ beta,
                                float* __restrict__ xn,
                                __nv_bfloat16* __restrict__ ahi,
                                __nv_bfloat16* __restrict__ alo) {
    int row = blockIdx.x;
    int tid = threadIdx.x;
    const float4* xr = reinterpret_cast<const float4*>(x + (size_t)row * DIM);
    float4 a = xr[tid];
    float4 b = xr[tid + 256];
    float s  = a.x + a.y + a.z + a.w + b.x + b.y + b.z + b.w;
    float s2 = a.x*a.x + a.y*a.y + a.z*a.z + a.w*a.w
             + b.x*b.x + b.y*b.y + b.z*b.z + b.w*b.w;
    #pragma unroll
    for (int off = 16; off > 0; off >>= 1) {
        s  += __shfl_xor_sync(0xffffffffu, s,  off);
        s2 += __shfl_xor_sync(0xffffffffu, s2, off);
    }
    __shared__ float ss[8], ss2[8];
    int wid = tid >> 5, lane = tid & 31;
    if (lane == 0) { ss[wid] = s; ss2[wid] = s2; }
    __syncthreads();
    s  = ss[0] + ss[1] + ss[2] + ss[3] + ss[4] + ss[5] + ss[6] + ss[7];
    s2 = ss2[0]+ ss2[1]+ ss2[2]+ ss2[3]+ ss2[4]+ ss2[5]+ ss2[6]+ ss2[7];
    float mean = s * (1.0f / DIM);
    float var  = s2 * (1.0f / DIM) - mean * mean;
    float rstd = rsqrtf(var + LN_EPS);

    const float4* g4 = reinterpret_cast<const float4*>(gamma);
    const float4* b4 = reinterpret_cast<const float4*>(beta);
    float4 g0 = g4[tid], g1 = g4[tid + 256];
    float4 be0 = b4[tid], be1 = b4[tid + 256];
    float4 o0, o1;
    o0.x = (a.x - mean) * rstd * g0.x + be0.x;
    o0.y = (a.y - mean) * rstd * g0.y + be0.y;
    o0.z = (a.z - mean) * rstd * g0.z + be0.z;
    o0.w = (a.w - mean) * rstd * g0.w + be0.w;
    o1.x = (b.x - mean) * rstd * g1.x + be1.x;
    o1.y = (b.y - mean) * rstd * g1.y + be1.y;
    o1.z = (b.z - mean) * rstd * g1.z + be1.z;
    o1.w = (b.w - mean) * rstd * g1.w + be1.w;
    float4* o4 = reinterpret_cast<float4*>(xn + (size_t)row * DIM);
    o4[tid] = o0;
    o4[tid + 256] = o1;

    __nv_bfloat162* ph = reinterpret_cast<__nv_bfloat162*>(ahi + (size_t)row * DIM);
    __nv_bfloat162* pl = reinterpret_cast<__nv_bfloat162*>(alo + (size_t)row * DIM);
    ph[tid*2+0]   = bf2hi(o0.x, o0.y);  pl[tid*2+0]   = bf2lo(o0.x, o0.y);
    ph[tid*2+1]   = bf2hi(o0.z, o0.w);  pl[tid*2+1]   = bf2lo(o0.z, o0.w);
    ph[tid*2+512] = bf2hi(o1.x, o1.y);  pl[tid*2+512] = bf2lo(o1.x, o1.y);
    ph[tid*2+513] = bf2hi(o1.z, o1.w);  pl[tid*2+513] = bf2lo(o1.z, o1.w);
}

// ---------------------------------------------------------------------------
// Kernel 2: transpose + bf16 split of weight matrices.
// ---------------------------------------------------------------------------
__global__ void tsplit_kernel(const float* __restrict__ src, int ld_src,
                              __nv_bfloat16* __restrict__ dhi,
                              __nv_bfloat16* __restrict__ dlo, int ld_dst) {
    __shared__ float t[32][33];
    int n0 = blockIdx.x * 32, k0 = blockIdx.y * 32;
    int tx = threadIdx.x, ty = threadIdx.y;
    #pragma unroll
    for (int i = 0; i < 4; i++)
        t[ty + 8*i][tx] = src[(size_t)(k0 + ty + 8*i) * ld_src + n0 + tx];
    __syncthreads();
    #pragma unroll
    for (int i = 0; i < 4; i++) {
        float v = t[tx][ty + 8*i];
        size_t o = (size_t)(n0 + ty + 8*i) * ld_dst + k0 + tx;
        __nv_bfloat16 h = __float2bfloat16(v);
        dhi[o] = h;
        dlo[o] = __float2bfloat16(v - __bfloat162float(h));
    }
}

// ---------------------------------------------------------------------------
// Tensor-core GEMM (mma.sync bf16, 3-term hi/lo split).
// CTA tile 128x128, K-chunk 32, 2-stage cp.async pipeline, 256 threads,
// 2 CTAs/SM (smem 80KB/CTA, regs capped at 128).
// Inner loop = 3 passes (Ahi*Bhi, Ahi*Blo, Alo*Bhi); one A-frag set live.
// ---------------------------------------------------------------------------
#define BK     32
#define SROWB  80            // bytes per smem row (32 bf16 + 4 pad)
#define OFF_ALO 10240
#define OFF_BHI 20480
#define OFF_BLO 30720
#define STAGEB  40960
#define NSTAGE  2

template <bool RES>
__global__ __launch_bounds__(256, 2) void gemm_mma(
        const __nv_bfloat16* __restrict__ Ahi, const __nv_bfloat16* __restrict__ Alo,
        const __nv_bfloat16* __restrict__ Bhi, const __nv_bfloat16* __restrict__ Blo,
        float* __restrict__ C, int K, int ldc, const float* __restrict__ resid) {
    extern __shared__ __align__(16) char dsm[];
    uint32_t sbase = smem_u32(dsm);

    int tid  = threadIdx.x;
    int wid  = tid >> 5;
    int lane = tid & 31;
    int wm   = wid & 3;          // M quarter (32 rows)
    int wn   = wid >> 2;         // N half   (64 cols)

    int m0 = blockIdx.x * 128;   // grid.x = M tiles -> wave shares B tiles
    int n0 = blockIdx.y * 128;

    // cp.async per-thread mapping: 512 16B-chunks per (sub)tile, 2 per thread
    uint32_t sO[2]; size_t gO[2];
    #pragma unroll
    for (int i = 0; i < 2; i++) {
        int idx = tid + i * 256;
        int row = idx >> 2, c = idx & 3;
        sO[i] = (uint32_t)(row * SROWB + c * 16);
        gO[i] = (size_t)row * K + c * 8;
    }
    const __nv_bfloat16* gAhi = Ahi + (size_t)m0 * K;
    const __nv_bfloat16* gAlo = Alo + (size_t)m0 * K;
    const __nv_bfloat16* gBhi = Bhi + (size_t)n0 * K;
    const __nv_bfloat16* gBlo = Blo + (size_t)n0 * K;

    const int NC = K / BK;

    auto load_chunk = [&](int c) {
        uint32_t base = sbase + (uint32_t)(c & 1) * STAGEB;
        size_t co = (size_t)c * BK;
        #pragma unroll
        for (int i = 0; i < 2; i++) {
            CP_ASYNC16(base + sO[i],           (const void*)(gAhi + gO[i] + co));
            CP_ASYNC16(base + OFF_ALO + sO[i], (const void*)(gAlo + gO[i] + co));
            CP_ASYNC16(base + OFF_BHI + sO[i], (const void*)(gBhi + gO[i] + co));
            CP_ASYNC16(base + OFF_BLO + sO[i], (const void*)(gBlo + gO[i] + co));
        }
    };

    float acc[2][8][4];
    #pragma unroll
    for (int i = 0; i < 2; i++)
        #pragma unroll
        for (int j = 0; j < 8; j++)
            #pragma unroll
            for (int v = 0; v < 4; v++) acc[i][j][v] = 0.0f;

    // prologue: fill pipeline (1 chunk)
    load_chunk(0);
    CP_COMMIT();

    uint32_t aBase = (uint32_t)((wm * 32 + (lane & 15)) * SROWB + (lane >> 4) * 16);
    uint32_t bBase = (uint32_t)((wn * 64 + (lane & 15)) * SROWB + (lane >> 4) * 16);

    for (int c = 0; c < NC; c++) {
        CP_WAIT(0);
        __syncthreads();
        if (c + 1 < NC) load_chunk(c + 1);
        CP_COMMIT();

        uint32_t buf = sbase + (uint32_t)(c & 1) * STAGEB;

        uint32_t aF[2][2][4];     // one A variant live at a time
        #pragma unroll
        for (int p = 0; p < 3; p++) {
            // pass 0: Ahi*Bhi, pass 1: Ahi*Blo, pass 2: Alo*Bhi
            if (p != 1) {
                uint32_t aoff = (p == 0) ? 0u : (uint32_t)OFF_ALO;
                #pragma unroll
                for (int mt = 0; mt < 2; mt++)
                    #pragma unroll
                    for (int ks = 0; ks < 2; ks++) {
                        uint32_t ad = buf + aoff + aBase + mt * (16 * SROWB) + ks * 32;
                        LDSM_X4(aF[mt][ks][0], aF[mt][ks][1], aF[mt][ks][2], aF[mt][ks][3], ad);
                    }
            }
            uint32_t boff = (p == 1) ? (uint32_t)OFF_BLO : (uint32_t)OFF_BHI;
            #pragma unroll
            for (int g = 0; g < 4; g++) {
                #pragma unroll
                for (int ks = 0; ks < 2; ks++) {
                    uint32_t bd = buf + boff + bBase + g * (16 * SROWB) + ks * 32;
                    uint32_t bf[4];
                    LDSM_X4(bf[0], bf[1], bf[2], bf[3], bd);
                    int nt0 = 2 * g, nt1 = 2 * g + 1;
                    MMA16816(acc[0][nt0], aF[0][ks][0], aF[0][ks][1], aF[0][ks][2], aF[0][ks][3], bf[0], bf[2]);
                    MMA16816(acc[0][nt1], aF[0][ks][0], aF[0][ks][1], aF[0][ks][2], aF[0][ks][3], bf[1], bf[3]);
                    MMA16816(acc[1][nt0], aF[1][ks][0], aF[1][ks][1], aF[1][ks][2], aF[1][ks][3], bf[0], bf[2]);
                    MMA16816(acc[1][nt1], aF[1][ks][0], aF[1][ks][1], aF[1][ks][2], aF[1][ks][3], bf[1], bf[3]);
                }
            }
        }
        __syncthreads();
    }

    // Epilogue
    int g = lane >> 2, q = lane & 3;
    #pragma unroll
    for (int mt = 0; mt < 2; mt++) {
        #pragma unroll
        for (int nt = 0; nt < 8; nt++) {
            int rowm = m0 + wm * 32 + mt * 16 + g;
            int coln = n0 + wn * 64 + nt * 8 + q * 2;
            float* p0 = C + (size_t)rowm * ldc + coln;
            float* p1 = C + (size_t)(rowm + 8) * ldc + coln;
            float2 v0 = make_float2(acc[mt][nt][0], acc[mt][nt][1]);
            float2 v1 = make_float2(acc[mt][nt][2], acc[mt][nt][3]);
            if (RES) {
                const float2 r0 = *reinterpret_cast<const float2*>(resid + (size_t)rowm * ldc + coln);
                const float2 r1 = *reinterpret_cast<const float2*>(resid + (size_t)(rowm + 8) * ldc + coln);
                v0.x += r0.x; v0.y += r0.y;
                v1.x += r1.x; v1.y += r1.y;
            }
            *reinterpret_cast<float2*>(p0) = v0;
            *reinterpret_cast<float2*>(p1) = v1;
        }
    }
}

// ---------------------------------------------------------------------------
// Kernel: rotary (in-place on q & k regions of g_h).
// q additionally scaled by QSCALE * log2(e) so softmax works in log2 domain.
// ---------------------------------------------------------------------------
__global__ void rotary_kernel(float* __restrict__ h) {
    int row = blockIdx.x;
    int s = row & (SEQ - 1);
    float* hp = h + (size_t)row * HCOLS;
    for (int job = threadIdx.x; job < 1056; job += blockDim.x) {
        int c, base;
        float scl;
        if (job < 1024) { int hd = job >> 5; c = job & 31; base = hd * 64; scl = QSCALE * LOG2E; }
        else            { c = job - 1024; base = NHEAD * DHEAD; scl = 1.0f; }
        float inv = powf(10000.0f, -(float)c * (1.0f / 32.0f));
        float ang = (float)s * inv;
        float sn, cs;
        sincosf(ang, &sn, &cs);
        float qa = hp[base + c];
        float qb = hp[base + c + 32];
        hp[base + c]      = (qa * cs - qb * sn) * scl;
        hp[base + c + 32] = (qb * cs + qa * sn) * scl;
    }
}

// ---------------------------------------------------------------------------
// Kernel: causal MQA flash attention (log2-domain softmax, poly exp2).
// ---------------------------------------------------------------------------
__global__ __launch_bounds__(128) void attn_kernel(
        const float* __restrict__ h,
        __nv_bfloat16* __restrict__ a2hi, __nv_bfloat16* __restrict__ a2lo) {
    __shared__ float4 ks4[64][16];
    __shared__ float4 vs4[64][16];
    int tid  = threadIdx.x;
    int r    = blockIdx.x * 128 + tid;
    int head = blockIdx.y;
    int b    = blockIdx.z;

    const float* qp = h + (size_t)(b * SEQ + r) * HCOLS + head * DHEAD;
    float4 q4[16];
    #pragma unroll
    for (int i = 0; i < 16; i++) q4[i] = reinterpret_cast<const float4*>(qp)[i];

    float4 acc[16];
    #pragma unroll
    for (int i = 0; i < 16; i++) acc[i] = make_float4(0.f, 0.f, 0.f, 0.f);
    float mrow = -INFINITY, lsum = 0.0f;

    int ntile = 2 * (blockIdx.x + 1);
    for (int t = 0; t < ntile; t++) {
        int j0 = t * 64;
        __syncthreads();
        #pragma unroll
        for (int it = 0; it < 8; it++) {
            int idx = tid + it * 128;
            int jr = idx >> 4, d4 = idx & 15;
            const float* kp = h + (size_t)(b * SEQ + j0 + jr) * HCOLS + NHEAD * DHEAD;
            ks4[jr][d4] = reinterpret_cast<const float4*>(kp)[d4];
            vs4[jr][d4] = reinterpret_cast<const float4*>(kp + DHEAD)[d4];
        }
        __syncthreads();
        int jend = r - j0 + 1;
        if (jend > 64) jend = 64;
        for (int j = 0; j < jend; j++) {
            float dot = 0.0f;
            #pragma unroll
            for (int i = 0; i < 16; i++) {
                float4 kv = ks4[j][i];
                dot += q4[i].x * kv.x + q4[i].y * kv.y + q4[i].z * kv.z + q4[i].w * kv.w;
            }
            if (dot <= mrow) {
                float p = exp2_poly(dot - mrow);
                lsum += p;
                #pragma unroll
                for (int i = 0; i < 16; i++) {
                    float4 vv = vs4[j][i];
                    acc[i].x += p * vv.x; acc[i].y += p * vv.y;
                    acc[i].z += p * vv.z; acc[i].w += p * vv.w;
                }
            } else {
                float sc = exp2_poly(mrow - dot);
                mrow = dot;
                lsum = lsum * sc + 1.0f;
                #pragma unroll
                for (int i = 0; i < 16; i++) {
                    float4 vv = vs4[j][i];
                    acc[i].x = acc[i].x * sc + vv.x; acc[i].y = acc[i].y * sc + vv.y;
                    acc[i].z = acc[i].z * sc + vv.z; acc[i].w = acc[i].w * sc + vv.w;
                }
            }
        }
    }
    float inv = 1.0f / lsum;
    size_t ob = (size_t)(b * SEQ + r) * OUTK + head * DHEAD;
    __nv_bfloat162* ph = reinterpret_cast<__nv_bfloat162*>(a2hi + ob);
    __nv_bfloat162* pl = reinterpret_cast<__nv_bfloat162*>(a2lo + ob);
    #pragma unroll
    for (int i = 0; i < 16; i++) {
        float4 o = acc[i];
        o.x *= inv; o.y *= inv; o.z *= inv; o.w *= inv;
        ph[i*2+0] = bf2hi(o.x, o.y);  pl[i*2+0] = bf2lo(o.x, o.y);
        ph[i*2+1] = bf2hi(o.z, o.w);  pl[i*2+1] = bf2lo(o.z, o.w);
    }
}

// ---------------------------------------------------------------------------
// Kernel: split ffn region of g_h into A2 cols [2048, 10240)
// ---------------------------------------------------------------------------
__global__ void ffn_split_kernel(const float* __restrict__ h,
                                 __nv_bfloat16* __restrict__ a2hi,
                                 __nv_bfloat16* __restrict__ a2lo) {
    size_t i = (size_t)blockIdx.x * blockDim.x + threadIdx.x;
    int m  = (int)(i >> 11);
    int j4 = (int)(i & 2047);
    float4 v = *reinterpret_cast<const float4*>(h + (size_t)m * HCOLS + 2176 + j4 * 4);
    size_t ob = (size_t)m * OUTK + 2048 + j4 * 4;
    __nv_bfloat162* ph = reinterpret_cast<__nv_bfloat162*>(a2hi + ob);
    __nv_bfloat162* pl = reinterpret_cast<__nv_bfloat162*>(a2lo + ob);
    ph[0] = bf2hi(v.x, v.y);  pl[0] = bf2lo(v.x, v.y);
    ph[1] = bf2hi(v.z, v.w);  pl[1] = bf2lo(v.z, v.w);
}

// ---------------------------------------------------------------------------
extern "C" void kernel_launch(void* const* d_in, const int* in_sizes, int n_in,
                              void* d_out, int out_size) {
    const float* x     = (const float*)d_in[0];
    const float* W_in  = (const float*)d_in[1];
    const float* W_out = (const float*)d_in[2];
    const float* gamma = (const float*)d_in[3];
    const float* beta  = (const float*)d_in[4];
    float* out = (float*)d_out;

    float* xn;  cudaGetSymbolAddress((void**)&xn,  g_xn);
    float* h;   cudaGetSymbolAddress((void**)&h,   g_h);
    __nv_bfloat16 *a1hi, *a1lo, *w1hi, *w1lo, *a2hi, *a2lo, *w2hi, *w2lo;
    cudaGetSymbolAddress((void**)&a1hi, g_a1hi);
    cudaGetSymbolAddress((void**)&a1lo, g_a1lo);
    cudaGetSymbolAddress((void**)&w1hi, g_w1hi);
    cudaGetSymbolAddress((void**)&w1lo, g_w1lo);
    cudaGetSymbolAddress((void**)&a2hi, g_a2hi);
    cudaGetSymbolAddress((void**)&a2lo, g_a2lo);
    cudaGetSymbolAddress((void**)&w2hi, g_w2hi);
    cudaGetSymbolAddress((void**)&w2lo, g_w2lo);

    const int SMEM = NSTAGE * STAGEB;   // 81920 -> 2 CTAs/SM
    cudaFuncSetAttribute(gemm_mma<false>, cudaFuncAttributeMaxDynamicSharedMemorySize, SMEM);
    cudaFuncSetAttribute(gemm_mma<true>,  cudaFuncAttributeMaxDynamicSharedMemorySize, SMEM);

    ln_split_kernel<<<MTOK, 256>>>(x, gamma, beta, xn, a1hi, a1lo);
    tsplit_kernel<<<dim3(HCOLS/32, DIM/32), dim3(32, 8)>>>(W_in, LDWIN, w1hi, w1lo, DIM);
    tsplit_kernel<<<dim3(DIM/32, OUTK/32), dim3(32, 8)>>>(W_out, DIM, w2hi, w2lo, OUTK);
    gemm_mma<false><<<dim3(MTOK/128, HCOLS/128), 256, SMEM>>>(
        a1hi, a1lo, w1hi, w1lo, h, DIM, HCOLS, nullptr);
    rotary_kernel<<<MTOK, 128>>>(h);
    attn_kernel<<<dim3(SEQ/128, NHEAD, BATCH), 128>>>(h, a2hi, a2lo);
    ffn_split_kernel<<<(MTOK * 2048) / 256, 256>>>(h, a2hi, a2lo);
    gemm_mma<true><<<dim3(MTOK/128, DIM/128), 256, SMEM>>>(
        a2hi, a2lo, w2hi, w2lo, out, OUTK, DIM, xn);
}

// round 6
// speedup vs baseline: 1.8717x; 1.7642x over previous
#include <cuda_runtime.h>
#include <cuda_fp16.h>
#include <math.h>
#include <stdint.h>

// ---------------------------------------------------------------------------
// Problem constants
// ---------------------------------------------------------------------------
#define BATCH 2
#define SEQ   2048
#define DIM   2048
#define NHEAD 32
#define DHEAD 64
#define FFN   8192
#define LDWIN 18560              // W_in row stride (full)
#define HCOLS 10368              // used cols of W_in: q|k|v|ffn
#define OUTK  10240              // concat dim: attn(2048)+ffn(8192)
#define MTOK  (BATCH*SEQ)
#define LN_EPS 1e-5f
#define QSCALE 0.125f
#define LOG2E  1.4426950408889634f

// ---------------------------------------------------------------------------
// Scratch (device globals)
// ---------------------------------------------------------------------------
__device__ float g_xn[(size_t)MTOK * DIM];      // LN output (residual)
__device__ float g_h[(size_t)MTOK * HCOLS];     // GEMM1 output fp32
__device__ __half g_a1[(size_t)MTOK * DIM];     // LN output fp16
__device__ __half g_w1[(size_t)HCOLS * DIM];    // W_in^T fp16 [10368,2048]
__device__ __half g_a2[(size_t)MTOK * OUTK];    // concat fp16 [4096,10240]
__device__ __half g_w2[(size_t)DIM * OUTK];     // W_out^T fp16 [2048,10240]

// ---------------------------------------------------------------------------
// PTX helpers
// ---------------------------------------------------------------------------
__device__ __forceinline__ uint32_t smem_u32(const void* p) {
    uint32_t a;
    asm("{ .reg .u64 t; cvta.to.shared.u64 t, %1; cvt.u32.u64 %0, t; }" : "=r"(a) : "l"(p));
    return a;
}
#define CP_ASYNC16(sa, gp) \
    asm volatile("cp.async.cg.shared.global [%0], [%1], 16;" :: "r"(sa), "l"(gp))
#define CP_COMMIT() asm volatile("cp.async.commit_group;" ::: "memory")
#define CP_WAIT(n)  asm volatile("cp.async.wait_group %0;" :: "n"(n) : "memory")

#define LDSM_X4(r0, r1, r2, r3, addr) \
    asm volatile("ldmatrix.sync.aligned.m8n8.x4.shared.b16 {%0,%1,%2,%3}, [%4];" \
        : "=r"(r0), "=r"(r1), "=r"(r2), "=r"(r3) : "r"(addr))

#define MMA16816(d, a0, a1, a2, a3, b0, b1) \
    asm volatile("mma.sync.aligned.m16n8k16.row.col.f32.f16.f16.f32 " \
        "{%0,%1,%2,%3}, {%4,%5,%6,%7}, {%8,%9}, {%0,%1,%2,%3};" \
        : "+f"((d)[0]), "+f"((d)[1]), "+f"((d)[2]), "+f"((d)[3]) \
        : "r"(a0), "r"(a1), "r"(a2), "r"(a3), "r"(b0), "r"(b1))

__device__ __forceinline__ __half2 h2(float x, float y) {
    return __halves2half2(__float2half_rn(x), __float2half_rn(y));
}

// Fast 2^t via FMA polynomial (no MUFU). Valid for t <= 0 (softmax domain).
__device__ __forceinline__ float exp2_poly(float t) {
    t = fmaxf(t, -60.0f);
    float fi = floorf(t);
    float f = t - fi;                 // [0,1)
    float p = 1.3333558e-3f;
    p = fmaf(p, f, 9.6181291e-3f);
    p = fmaf(p, f, 5.5504109e-2f);
    p = fmaf(p, f, 2.4022651e-1f);
    p = fmaf(p, f, 6.9314718e-1f);
    p = fmaf(p, f, 1.0f);
    float s = __int_as_float(((int)fi + 127) << 23);
    return s * p;
}

// ---------------------------------------------------------------------------
// Kernel 1: LayerNorm -> xn (fp32 residual) + a1 (fp16 GEMM1 operand)
// ---------------------------------------------------------------------------
__global__ void ln_split_kernel(const float* __restrict__ x,
                                const float* __restrict__ gamma,
                                const float* __restrict__ beta,
                                float* __restrict__ xn,
                                __half* __restrict__ a1) {
    int row = blockIdx.x;
    int tid = threadIdx.x;
    const float4* xr = reinterpret_cast<const float4*>(x + (size_t)row * DIM);
    float4 a = xr[tid];
    float4 b = xr[tid + 256];
    float s  = a.x + a.y + a.z + a.w + b.x + b.y + b.z + b.w;
    float s2 = a.x*a.x + a.y*a.y + a.z*a.z + a.w*a.w
             + b.x*b.x + b.y*b.y + b.z*b.z + b.w*b.w;
    #pragma unroll
    for (int off = 16; off > 0; off >>= 1) {
        s  += __shfl_xor_sync(0xffffffffu, s,  off);
        s2 += __shfl_xor_sync(0xffffffffu, s2, off);
    }
    __shared__ float ss[8], ss2[8];
    int wid = tid >> 5, lane = tid & 31;
    if (lane == 0) { ss[wid] = s; ss2[wid] = s2; }
    __syncthreads();
    s  = ss[0] + ss[1] + ss[2] + ss[3] + ss[4] + ss[5] + ss[6] + ss[7];
    s2 = ss2[0]+ ss2[1]+ ss2[2]+ ss2[3]+ ss2[4]+ ss2[5]+ ss2[6]+ ss2[7];
    float mean = s * (1.0f / DIM);
    float var  = s2 * (1.0f / DIM) - mean * mean;
    float rstd = rsqrtf(var + LN_EPS);

    const float4* g4 = reinterpret_cast<const float4*>(gamma);
    const float4* b4 = reinterpret_cast<const float4*>(beta);
    float4 g0 = g4[tid], g1 = g4[tid + 256];
    float4 be0 = b4[tid], be1 = b4[tid + 256];
    float4 o0, o1;
    o0.x = (a.x - mean) * rstd * g0.x + be0.x;
    o0.y = (a.y - mean) * rstd * g0.y + be0.y;
    o0.z = (a.z - mean) * rstd * g0.z + be0.z;
    o0.w = (a.w - mean) * rstd * g0.w + be0.w;
    o1.x = (b.x - mean) * rstd * g1.x + be1.x;
    o1.y = (b.y - mean) * rstd * g1.y + be1.y;
    o1.z = (b.z - mean) * rstd * g1.z + be1.z;
    o1.w = (b.w - mean) * rstd * g1.w + be1.w;
    float4* o4 = reinterpret_cast<float4*>(xn + (size_t)row * DIM);
    o4[tid] = o0;
    o4[tid + 256] = o1;

    __half2* ph = reinterpret_cast<__half2*>(a1 + (size_t)row * DIM);
    ph[tid*2+0]   = h2(o0.x, o0.y);
    ph[tid*2+1]   = h2(o0.z, o0.w);
    ph[tid*2+512] = h2(o1.x, o1.y);
    ph[tid*2+513] = h2(o1.z, o1.w);
}

// ---------------------------------------------------------------------------
// Kernel 2: transpose + fp16 convert of weight matrices. dst[n][k] = src[k][n].
// ---------------------------------------------------------------------------
__global__ void tsplit_kernel(const float* __restrict__ src, int ld_src,
                              __half* __restrict__ dst, int ld_dst) {
    __shared__ float t[32][33];
    int n0 = blockIdx.x * 32, k0 = blockIdx.y * 32;
    int tx = threadIdx.x, ty = threadIdx.y;
    #pragma unroll
    for (int i = 0; i < 4; i++)
        t[ty + 8*i][tx] = src[(size_t)(k0 + ty + 8*i) * ld_src + n0 + tx];
    __syncthreads();
    #pragma unroll
    for (int i = 0; i < 4; i++) {
        float v = t[tx][ty + 8*i];
        dst[(size_t)(n0 + ty + 8*i) * ld_dst + k0 + tx] = __float2half_rn(v);
    }
}

// ---------------------------------------------------------------------------
// Tensor-core GEMM (mma.sync fp16, single pass, fp32 accum).
// C[M,N] = A[M,K] @ B^T ([N,K] K-major).
// CTA tile 128x128, K-chunk 32, 4-stage cp.async pipeline, 256 threads,
// 2 CTAs/SM (smem 80KB/CTA, regs capped at 128).
// ---------------------------------------------------------------------------
#define BK     32
#define SROWB  80            // bytes per smem row (32 fp16 + 8 pad)
#define OFF_B  10240
#define STAGEB 20480
#define NSTAGE 4

template <bool RES>
__global__ __launch_bounds__(256, 2) void gemm_mma(
        const __half* __restrict__ A, const __half* __restrict__ B,
        float* __restrict__ C, int K, int ldc, const float* __restrict__ resid) {
    extern __shared__ __align__(16) char dsm[];
    uint32_t sbase = smem_u32(dsm);

    int tid  = threadIdx.x;
    int wid  = tid >> 5;
    int lane = tid & 31;
    int wm   = wid & 3;          // M quarter (32 rows)
    int wn   = wid >> 2;         // N half   (64 cols)

    int m0 = blockIdx.x * 128;   // grid.x = M tiles -> wave shares B tiles
    int n0 = blockIdx.y * 128;

    // cp.async per-thread mapping: 512 16B-chunks per tile, 2 per thread
    uint32_t sO[2]; size_t gO[2];
    #pragma unroll
    for (int i = 0; i < 2; i++) {
        int idx = tid + i * 256;
        int row = idx >> 2, c = idx & 3;
        sO[i] = (uint32_t)(row * SROWB + c * 16);
        gO[i] = (size_t)row * K + c * 8;
    }
    const __half* gA = A + (size_t)m0 * K;
    const __half* gB = B + (size_t)n0 * K;

    const int NC = K / BK;

    auto load_chunk = [&](int c) {
        uint32_t base = sbase + (uint32_t)(c % NSTAGE) * STAGEB;
        size_t co = (size_t)c * BK;
        #pragma unroll
        for (int i = 0; i < 2; i++) {
            CP_ASYNC16(base + sO[i],         (const void*)(gA + gO[i] + co));
            CP_ASYNC16(base + OFF_B + sO[i], (const void*)(gB + gO[i] + co));
        }
    };

    float acc[2][8][4];
    #pragma unroll
    for (int i = 0; i < 2; i++)
        #pragma unroll
        for (int j = 0; j < 8; j++)
            #pragma unroll
            for (int v = 0; v < 4; v++) acc[i][j][v] = 0.0f;

    // prologue: fill pipeline (3 chunks)
    #pragma unroll
    for (int c = 0; c < NSTAGE - 1; c++) { load_chunk(c); CP_COMMIT(); }

    uint32_t aBase = (uint32_t)((wm * 32 + (lane & 15)) * SROWB + (lane >> 4) * 16);
    uint32_t bBase = (uint32_t)((wn * 64 + (lane & 15)) * SROWB + (lane >> 4) * 16);

    for (int c = 0; c < NC; c++) {
        CP_WAIT(NSTAGE - 2);
        __syncthreads();
        if (c + NSTAGE - 1 < NC) load_chunk(c + NSTAGE - 1);
        CP_COMMIT();

        uint32_t buf = sbase + (uint32_t)(c % NSTAGE) * STAGEB;

        #pragma unroll
        for (int ks = 0; ks < 2; ks++) {
            uint32_t aF[2][4];
            #pragma unroll
            for (int mt = 0; mt < 2; mt++) {
                uint32_t ad = buf + aBase + mt * (16 * SROWB) + ks * 32;
                LDSM_X4(aF[mt][0], aF[mt][1], aF[mt][2], aF[mt][3], ad);
            }
            #pragma unroll
            for (int g = 0; g < 4; g++) {
                uint32_t bd = buf + OFF_B + bBase + g * (16 * SROWB) + ks * 32;
                uint32_t bf[4];
                LDSM_X4(bf[0], bf[1], bf[2], bf[3], bd);
                int nt0 = 2 * g, nt1 = 2 * g + 1;
                MMA16816(acc[0][nt0], aF[0][0], aF[0][1], aF[0][2], aF[0][3], bf[0], bf[2]);
                MMA16816(acc[0][nt1], aF[0][0], aF[0][1], aF[0][2], aF[0][3], bf[1], bf[3]);
                MMA16816(acc[1][nt0], aF[1][0], aF[1][1], aF[1][2], aF[1][3], bf[0], bf[2]);
                MMA16816(acc[1][nt1], aF[1][0], aF[1][1], aF[1][2], aF[1][3], bf[1], bf[3]);
            }
        }
    }

    // Epilogue
    int g = lane >> 2, q = lane & 3;
    #pragma unroll
    for (int mt = 0; mt < 2; mt++) {
        #pragma unroll
        for (int nt = 0; nt < 8; nt++) {
            int rowm = m0 + wm * 32 + mt * 16 + g;
            int coln = n0 + wn * 64 + nt * 8 + q * 2;
            float* p0 = C + (size_t)rowm * ldc + coln;
            float* p1 = C + (size_t)(rowm + 8) * ldc + coln;
            float2 v0 = make_float2(acc[mt][nt][0], acc[mt][nt][1]);
            float2 v1 = make_float2(acc[mt][nt][2], acc[mt][nt][3]);
            if (RES) {
                const float2 r0 = *reinterpret_cast<const float2*>(resid + (size_t)rowm * ldc + coln);
                const float2 r1 = *reinterpret_cast<const float2*>(resid + (size_t)(rowm + 8) * ldc + coln);
                v0.x += r0.x; v0.y += r0.y;
                v1.x += r1.x; v1.y += r1.y;
            }
            *reinterpret_cast<float2*>(p0) = v0;
            *reinterpret_cast<float2*>(p1) = v1;
        }
    }
}

// ---------------------------------------------------------------------------
// Kernel: rotary (in-place on q & k regions of g_h).
// q additionally scaled by QSCALE * log2(e) so softmax works in log2 domain.
// ---------------------------------------------------------------------------
__global__ void rotary_kernel(float* __restrict__ h) {
    int row = blockIdx.x;
    int s = row & (SEQ - 1);
    float* hp = h + (size_t)row * HCOLS;
    for (int job = threadIdx.x; job < 1056; job += blockDim.x) {
        int c, base;
        float scl;
        if (job < 1024) { int hd = job >> 5; c = job & 31; base = hd * 64; scl = QSCALE * LOG2E; }
        else            { c = job - 1024; base = NHEAD * DHEAD; scl = 1.0f; }
        float inv = powf(10000.0f, -(float)c * (1.0f / 32.0f));
        float ang = (float)s * inv;
        float sn, cs;
        sincosf(ang, &sn, &cs);
        float qa = hp[base + c];
        float qb = hp[base + c + 32];
        hp[base + c]      = (qa * cs - qb * sn) * scl;
        hp[base + c + 32] = (qb * cs + qa * sn) * scl;
    }
}

// ---------------------------------------------------------------------------
// Kernel: causal MQA flash attention (log2-domain softmax, poly exp2).
// Writes fp16 directly into A2 cols [0, 2048).
// ---------------------------------------------------------------------------
__global__ __launch_bounds__(128) void attn_kernel(
        const float* __restrict__ h, __half* __restrict__ a2) {
    __shared__ float4 ks4[64][16];
    __shared__ float4 vs4[64][16];
    int tid  = threadIdx.x;
    int r    = blockIdx.x * 128 + tid;
    int head = blockIdx.y;
    int b    = blockIdx.z;

    const float* qp = h + (size_t)(b * SEQ + r) * HCOLS + head * DHEAD;
    float4 q4[16];
    #pragma unroll
    for (int i = 0; i < 16; i++) q4[i] = reinterpret_cast<const float4*>(qp)[i];

    float4 acc[16];
    #pragma unroll
    for (int i = 0; i < 16; i++) acc[i] = make_float4(0.f, 0.f, 0.f, 0.f);
    float mrow = -INFINITY, lsum = 0.0f;

    int ntile = 2 * (blockIdx.x + 1);
    for (int t = 0; t < ntile; t++) {
        int j0 = t * 64;
        __syncthreads();
        #pragma unroll
        for (int it = 0; it < 8; it++) {
            int idx = tid + it * 128;
            int jr = idx >> 4, d4 = idx & 15;
            const float* kp = h + (size_t)(b * SEQ + j0 + jr) * HCOLS + NHEAD * DHEAD;
            ks4[jr][d4] = reinterpret_cast<const float4*>(kp)[d4];
            vs4[jr][d4] = reinterpret_cast<const float4*>(kp + DHEAD)[d4];
        }
        __syncthreads();
        int jend = r - j0 + 1;
        if (jend > 64) jend = 64;
        for (int j = 0; j < jend; j++) {
            float dot = 0.0f;
            #pragma unroll
            for (int i = 0; i < 16; i++) {
                float4 kv = ks4[j][i];
                dot += q4[i].x * kv.x + q4[i].y * kv.y + q4[i].z * kv.z + q4[i].w * kv.w;
            }
            if (dot <= mrow) {
                float p = exp2_poly(dot - mrow);
                lsum += p;
                #pragma unroll
                for (int i = 0; i < 16; i++) {
                    float4 vv = vs4[j][i];
                    acc[i].x += p * vv.x; acc[i].y += p * vv.y;
                    acc[i].z += p * vv.z; acc[i].w += p * vv.w;
                }
            } else {
                float sc = exp2_poly(mrow - dot);
                mrow = dot;
                lsum = lsum * sc + 1.0f;
                #pragma unroll
                for (int i = 0; i < 16; i++) {
                    float4 vv = vs4[j][i];
                    acc[i].x = acc[i].x * sc + vv.x; acc[i].y = acc[i].y * sc + vv.y;
                    acc[i].z = acc[i].z * sc + vv.z; acc[i].w = acc[i].w * sc + vv.w;
                }
            }
        }
    }
    float inv = 1.0f / lsum;
    size_t ob = (size_t)(b * SEQ + r) * OUTK + head * DHEAD;
    __half2* ph = reinterpret_cast<__half2*>(a2 + ob);
    #pragma unroll
    for (int i = 0; i < 16; i++) {
        float4 o = acc[i];
        o.x *= inv; o.y *= inv; o.z *= inv; o.w *= inv;
        ph[i*2+0] = h2(o.x, o.y);
        ph[i*2+1] = h2(o.z, o.w);
    }
}

// ---------------------------------------------------------------------------
// Kernel: convert ffn region of g_h into A2 cols [2048, 10240) as fp16
// ---------------------------------------------------------------------------
__global__ void ffn_split_kernel(const float* __restrict__ h,
                                 __half* __restrict__ a2) {
    size_t i = (size_t)blockIdx.x * blockDim.x + threadIdx.x;
    int m  = (int)(i >> 11);
    int j4 = (int)(i & 2047);
    float4 v = *reinterpret_cast<const float4*>(h + (size_t)m * HCOLS + 2176 + j4 * 4);
    size_t ob = (size_t)m * OUTK + 2048 + j4 * 4;
    __half2* ph = reinterpret_cast<__half2*>(a2 + ob);
    ph[0] = h2(v.x, v.y);
    ph[1] = h2(v.z, v.w);
}

// ---------------------------------------------------------------------------
extern "C" void kernel_launch(void* const* d_in, const int* in_sizes, int n_in,
                              void* d_out, int out_size) {
    const float* x     = (const float*)d_in[0];
    const float* W_in  = (const float*)d_in[1];
    const float* W_out = (const float*)d_in[2];
    const float* gamma = (const float*)d_in[3];
    const float* beta  = (const float*)d_in[4];
    float* out = (float*)d_out;

    float* xn;  cudaGetSymbolAddress((void**)&xn,  g_xn);
    float* h;   cudaGetSymbolAddress((void**)&h,   g_h);
    __half *a1, *w1, *a2, *w2;
    cudaGetSymbolAddress((void**)&a1, g_a1);
    cudaGetSymbolAddress((void**)&w1, g_w1);
    cudaGetSymbolAddress((void**)&a2, g_a2);
    cudaGetSymbolAddress((void**)&w2, g_w2);

    const int SMEM = NSTAGE * STAGEB;   // 81920 -> 2 CTAs/SM
    cudaFuncSetAttribute(gemm_mma<false>, cudaFuncAttributeMaxDynamicSharedMemorySize, SMEM);
    cudaFuncSetAttribute(gemm_mma<true>,  cudaFuncAttributeMaxDynamicSharedMemorySize, SMEM);

    ln_split_kernel<<<MTOK, 256>>>(x, gamma, beta, xn, a1);
    tsplit_kernel<<<dim3(HCOLS/32, DIM/32), dim3(32, 8)>>>(W_in, LDWIN, w1, DIM);
    tsplit_kernel<<<dim3(DIM/32, OUTK/32), dim3(32, 8)>>>(W_out, DIM, w2, OUTK);
    gemm_mma<false><<<dim3(MTOK/128, HCOLS/128), 256, SMEM>>>(
        a1, w1, h, DIM, HCOLS, nullptr);
    rotary_kernel<<<MTOK, 128>>>(h);
    attn_kernel<<<dim3(SEQ/128, NHEAD, BATCH), 128>>>(h, a2);
    ffn_split_kernel<<<(MTOK * 2048) / 256, 256>>>(h, a2);
    gemm_mma<true><<<dim3(MTOK/128, DIM/128), 256, SMEM>>>(
        a2, w2, out, OUTK, DIM, xn);
}

// round 7
// speedup vs baseline: 3.6996x; 1.9766x over previous
#include <cuda_runtime.h>
#include <cuda_fp16.h>
#include <math.h>
#include <stdint.h>

// ---------------------------------------------------------------------------
// Problem constants
// ---------------------------------------------------------------------------
#define BATCH 2
#define SEQ   2048
#define DIM   2048
#define NHEAD 32
#define DHEAD 64
#define FFN   8192
#define LDWIN 18560              // W_in row stride (full)
#define HCOLS 10368              // used cols of W_in: q|k|v|ffn
#define OUTK  10240              // concat dim: attn(2048)+ffn(8192)
#define MTOK  (BATCH*SEQ)
#define LN_EPS 1e-5f
#define QSCALE 0.125f
#define LOG2E  1.4426950408889634f

// ---------------------------------------------------------------------------
// Scratch (device globals)
// ---------------------------------------------------------------------------
__device__ float g_xn[(size_t)MTOK * DIM];      // LN output (residual)
__device__ float g_h[(size_t)MTOK * HCOLS];     // GEMM1 output fp32
__device__ __half g_a1[(size_t)MTOK * DIM];     // LN output fp16
__device__ __half g_w1[(size_t)HCOLS * DIM];    // W_in^T fp16 [10368,2048]
__device__ __half g_a2[(size_t)MTOK * OUTK];    // concat fp16 [4096,10240]
__device__ __half g_w2[(size_t)DIM * OUTK];     // W_out^T fp16 [2048,10240]
__device__ __half g_q16[(size_t)MTOK * DIM];    // rotated+scaled Q [b][h][s][d]
__device__ __half g_k16[(size_t)MTOK * DHEAD];  // rotated K [b][s][d]
__device__ __half g_vT[(size_t)MTOK * DHEAD];   // V transposed [b][d][s]

// ---------------------------------------------------------------------------
// PTX helpers
// ---------------------------------------------------------------------------
__device__ __forceinline__ uint32_t smem_u32(const void* p) {
    uint32_t a;
    asm("{ .reg .u64 t; cvta.to.shared.u64 t, %1; cvt.u32.u64 %0, t; }" : "=r"(a) : "l"(p));
    return a;
}
#define CP_ASYNC16(sa, gp) \
    asm volatile("cp.async.cg.shared.global [%0], [%1], 16;" :: "r"(sa), "l"(gp))
#define CP_COMMIT() asm volatile("cp.async.commit_group;" ::: "memory")
#define CP_WAIT(n)  asm volatile("cp.async.wait_group %0;" :: "n"(n) : "memory")

#define LDSM_X4(r0, r1, r2, r3, addr) \
    asm volatile("ldmatrix.sync.aligned.m8n8.x4.shared.b16 {%0,%1,%2,%3}, [%4];" \
        : "=r"(r0), "=r"(r1), "=r"(r2), "=r"(r3) : "r"(addr))

#define MMA16816(d, a0, a1, a2, a3, b0, b1) \
    asm volatile("mma.sync.aligned.m16n8k16.row.col.f32.f16.f16.f32 " \
        "{%0,%1,%2,%3}, {%4,%5,%6,%7}, {%8,%9}, {%0,%1,%2,%3};" \
        : "+f"((d)[0]), "+f"((d)[1]), "+f"((d)[2]), "+f"((d)[3]) \
        : "r"(a0), "r"(a1), "r"(a2), "r"(a3), "r"(b0), "r"(b1))

__device__ __forceinline__ __half2 h2(float x, float y) {
    return __halves2half2(__float2half_rn(x), __float2half_rn(y));
}
__device__ __forceinline__ uint32_t packh2(float x, float y) {
    __half2 v = __floats2half2_rn(x, y);
    return *reinterpret_cast<uint32_t*>(&v);
}

// Fast 2^t via FMA polynomial (no MUFU). Valid for t <= 0 (softmax domain).
__device__ __forceinline__ float exp2_poly(float t) {
    t = fmaxf(t, -60.0f);
    float fi = floorf(t);
    float f = t - fi;                 // [0,1)
    float p = 1.3333558e-3f;
    p = fmaf(p, f, 9.6181291e-3f);
    p = fmaf(p, f, 5.5504109e-2f);
    p = fmaf(p, f, 2.4022651e-1f);
    p = fmaf(p, f, 6.9314718e-1f);
    p = fmaf(p, f, 1.0f);
    float s = __int_as_float(((int)fi + 127) << 23);
    return s * p;
}

// ---------------------------------------------------------------------------
// Kernel 1: LayerNorm -> xn (fp32 residual) + a1 (fp16 GEMM1 operand)
// ---------------------------------------------------------------------------
__global__ void ln_split_kernel(const float* __restrict__ x,
                                const float* __restrict__ gamma,
                                const float* __restrict__ beta,
                                float* __restrict__ xn,
                                __half* __restrict__ a1) {
    int row = blockIdx.x;
    int tid = threadIdx.x;
    const float4* xr = reinterpret_cast<const float4*>(x + (size_t)row * DIM);
    float4 a = xr[tid];
    float4 b = xr[tid + 256];
    float s  = a.x + a.y + a.z + a.w + b.x + b.y + b.z + b.w;
    float s2 = a.x*a.x + a.y*a.y + a.z*a.z + a.w*a.w
             + b.x*b.x + b.y*b.y + b.z*b.z + b.w*b.w;
    #pragma unroll
    for (int off = 16; off > 0; off >>= 1) {
        s  += __shfl_xor_sync(0xffffffffu, s,  off);
        s2 += __shfl_xor_sync(0xffffffffu, s2, off);
    }
    __shared__ float ss[8], ss2[8];
    int wid = tid >> 5, lane = tid & 31;
    if (lane == 0) { ss[wid] = s; ss2[wid] = s2; }
    __syncthreads();
    s  = ss[0] + ss[1] + ss[2] + ss[3] + ss[4] + ss[5] + ss[6] + ss[7];
    s2 = ss2[0]+ ss2[1]+ ss2[2]+ ss2[3]+ ss2[4]+ ss2[5]+ ss2[6]+ ss2[7];
    float mean = s * (1.0f / DIM);
    float var  = s2 * (1.0f / DIM) - mean * mean;
    float rstd = rsqrtf(var + LN_EPS);

    const float4* g4 = reinterpret_cast<const float4*>(gamma);
    const float4* b4 = reinterpret_cast<const float4*>(beta);
    float4 g0 = g4[tid], g1 = g4[tid + 256];
    float4 be0 = b4[tid], be1 = b4[tid + 256];
    float4 o0, o1;
    o0.x = (a.x - mean) * rstd * g0.x + be0.x;
    o0.y = (a.y - mean) * rstd * g0.y + be0.y;
    o0.z = (a.z - mean) * rstd * g0.z + be0.z;
    o0.w = (a.w - mean) * rstd * g0.w + be0.w;
    o1.x = (b.x - mean) * rstd * g1.x + be1.x;
    o1.y = (b.y - mean) * rstd * g1.y + be1.y;
    o1.z = (b.z - mean) * rstd * g1.z + be1.z;
    o1.w = (b.w - mean) * rstd * g1.w + be1.w;
    float4* o4 = reinterpret_cast<float4*>(xn + (size_t)row * DIM);
    o4[tid] = o0;
    o4[tid + 256] = o1;

    __half2* ph = reinterpret_cast<__half2*>(a1 + (size_t)row * DIM);
    ph[tid*2+0]   = h2(o0.x, o0.y);
    ph[tid*2+1]   = h2(o0.z, o0.w);
    ph[tid*2+512] = h2(o1.x, o1.y);
    ph[tid*2+513] = h2(o1.z, o1.w);
}

// ---------------------------------------------------------------------------
// Kernel 2: transpose + fp16 convert of weight matrices. dst[n][k] = src[k][n].
// ---------------------------------------------------------------------------
__global__ void tsplit_kernel(const float* __restrict__ src, int ld_src,
                              __half* __restrict__ dst, int ld_dst) {
    __shared__ float t[32][33];
    int n0 = blockIdx.x * 32, k0 = blockIdx.y * 32;
    int tx = threadIdx.x, ty = threadIdx.y;
    #pragma unroll
    for (int i = 0; i < 4; i++)
        t[ty + 8*i][tx] = src[(size_t)(k0 + ty + 8*i) * ld_src + n0 + tx];
    __syncthreads();
    #pragma unroll
    for (int i = 0; i < 4; i++) {
        float v = t[tx][ty + 8*i];
        dst[(size_t)(n0 + ty + 8*i) * ld_dst + k0 + tx] = __float2half_rn(v);
    }
}

// ---------------------------------------------------------------------------
// Tensor-core GEMM (mma.sync fp16, single pass, fp32 accum). Same as R6.
// ---------------------------------------------------------------------------
#define BK     32
#define SROWB  80
#define OFF_B  10240
#define STAGEB 20480
#define NSTAGE 4

template <bool RES>
__global__ __launch_bounds__(256, 2) void gemm_mma(
        const __half* __restrict__ A, const __half* __restrict__ B,
        float* __restrict__ C, int K, int ldc, const float* __restrict__ resid) {
    extern __shared__ __align__(16) char dsm[];
    uint32_t sbase = smem_u32(dsm);

    int tid  = threadIdx.x;
    int wid  = tid >> 5;
    int lane = tid & 31;
    int wm   = wid & 3;
    int wn   = wid >> 2;

    int m0 = blockIdx.x * 128;
    int n0 = blockIdx.y * 128;

    uint32_t sO[2]; size_t gO[2];
    #pragma unroll
    for (int i = 0; i < 2; i++) {
        int idx = tid + i * 256;
        int row = idx >> 2, c = idx & 3;
        sO[i] = (uint32_t)(row * SROWB + c * 16);
        gO[i] = (size_t)row * K + c * 8;
    }
    const __half* gA = A + (size_t)m0 * K;
    const __half* gB = B + (size_t)n0 * K;

    const int NC = K / BK;

    auto load_chunk = [&](int c) {
        uint32_t base = sbase + (uint32_t)(c % NSTAGE) * STAGEB;
        size_t co = (size_t)c * BK;
        #pragma unroll
        for (int i = 0; i < 2; i++) {
            CP_ASYNC16(base + sO[i],         (const void*)(gA + gO[i] + co));
            CP_ASYNC16(base + OFF_B + sO[i], (const void*)(gB + gO[i] + co));
        }
    };

    float acc[2][8][4];
    #pragma unroll
    for (int i = 0; i < 2; i++)
        #pragma unroll
        for (int j = 0; j < 8; j++)
            #pragma unroll
            for (int v = 0; v < 4; v++) acc[i][j][v] = 0.0f;

    #pragma unroll
    for (int c = 0; c < NSTAGE - 1; c++) { load_chunk(c); CP_COMMIT(); }

    uint32_t aBase = (uint32_t)((wm * 32 + (lane & 15)) * SROWB + (lane >> 4) * 16);
    uint32_t bBase = (uint32_t)((wn * 64 + (lane & 15)) * SROWB + (lane >> 4) * 16);

    for (int c = 0; c < NC; c++) {
        CP_WAIT(NSTAGE - 2);
        __syncthreads();
        if (c + NSTAGE - 1 < NC) load_chunk(c + NSTAGE - 1);
        CP_COMMIT();

        uint32_t buf = sbase + (uint32_t)(c % NSTAGE) * STAGEB;

        #pragma unroll
        for (int ks = 0; ks < 2; ks++) {
            uint32_t aF[2][4];
            #pragma unroll
            for (int mt = 0; mt < 2; mt++) {
                uint32_t ad = buf + aBase + mt * (16 * SROWB) + ks * 32;
                LDSM_X4(aF[mt][0], aF[mt][1], aF[mt][2], aF[mt][3], ad);
            }
            #pragma unroll
            for (int g = 0; g < 4; g++) {
                uint32_t bd = buf + OFF_B + bBase + g * (16 * SROWB) + ks * 32;
                uint32_t bf[4];
                LDSM_X4(bf[0], bf[1], bf[2], bf[3], bd);
                int nt0 = 2 * g, nt1 = 2 * g + 1;
                MMA16816(acc[0][nt0], aF[0][0], aF[0][1], aF[0][2], aF[0][3], bf[0], bf[2]);
                MMA16816(acc[0][nt1], aF[0][0], aF[0][1], aF[0][2], aF[0][3], bf[1], bf[3]);
                MMA16816(acc[1][nt0], aF[1][0], aF[1][1], aF[1][2], aF[1][3], bf[0], bf[2]);
                MMA16816(acc[1][nt1], aF[1][0], aF[1][1], aF[1][2], aF[1][3], bf[1], bf[3]);
            }
        }
    }

    int g = lane >> 2, q = lane & 3;
    #pragma unroll
    for (int mt = 0; mt < 2; mt++) {
        #pragma unroll
        for (int nt = 0; nt < 8; nt++) {
            int rowm = m0 + wm * 32 + mt * 16 + g;
            int coln = n0 + wn * 64 + nt * 8 + q * 2;
            float* p0 = C + (size_t)rowm * ldc + coln;
            float* p1 = C + (size_t)(rowm + 8) * ldc + coln;
            float2 v0 = make_float2(acc[mt][nt][0], acc[mt][nt][1]);
            float2 v1 = make_float2(acc[mt][nt][2], acc[mt][nt][3]);
            if (RES) {
                const float2 r0 = *reinterpret_cast<const float2*>(resid + (size_t)rowm * ldc + coln);
                const float2 r1 = *reinterpret_cast<const float2*>(resid + (size_t)(rowm + 8) * ldc + coln);
                v0.x += r0.x; v0.y += r0.y;
                v1.x += r1.x; v1.y += r1.y;
            }
            *reinterpret_cast<float2*>(p0) = v0;
            *reinterpret_cast<float2*>(p1) = v1;
        }
    }
}

// ---------------------------------------------------------------------------
// Kernel: qkv prep. Rotary on q (scaled by QSCALE*log2e) and k; v transposed.
// Writes fp16: q16 [b][h][s][d], k16 [b][s][d], vT [b][d][s].
// ---------------------------------------------------------------------------
__global__ __launch_bounds__(128) void qkv_prep_kernel(
        const float* __restrict__ h,
        __half* __restrict__ q16, __half* __restrict__ k16,
        __half* __restrict__ vT) {
    int row = blockIdx.x;
    int b = row >> 11;
    int s = row & (SEQ - 1);
    const float* hp = h + (size_t)row * HCOLS;
    int tid = threadIdx.x;

    // q: 1024 rotation pairs
    for (int i = tid; i < 1024; i += 128) {
        int hd = i >> 5, c = i & 31;
        float inv = powf(10000.0f, -(float)c * (1.0f / 32.0f));
        float ang = (float)s * inv;
        float sn, cs;
        sincosf(ang, &sn, &cs);
        float qa = hp[hd * 64 + c], qb = hp[hd * 64 + c + 32];
        const float scl = QSCALE * LOG2E;
        __half* qd = q16 + ((size_t)(b * NHEAD + hd) * SEQ + s) * DHEAD;
        qd[c]      = __float2half_rn((qa * cs - qb * sn) * scl);
        qd[c + 32] = __float2half_rn((qb * cs + qa * sn) * scl);
    }
    // k: 32 rotation pairs
    if (tid < 32) {
        int c = tid;
        float inv = powf(10000.0f, -(float)c * (1.0f / 32.0f));
        float ang = (float)s * inv;
        float sn, cs;
        sincosf(ang, &sn, &cs);
        float ka = hp[2048 + c], kb = hp[2048 + c + 32];
        __half* kd = k16 + ((size_t)b * SEQ + s) * DHEAD;
        kd[c]      = __float2half_rn(ka * cs - kb * sn);
        kd[c + 32] = __float2half_rn(kb * cs + ka * sn);
    }
    // v: 64 elements, transposed layout
    if (tid >= 64) {
        int d = tid - 64;
        vT[((size_t)b * DHEAD + d) * SEQ + s] = __float2half_rn(hp[2112 + d]);
    }
}

// ---------------------------------------------------------------------------
// Tensor-core causal MQA flash attention.
// Grid (S/64, H, B), 128 threads. Q tile 64x64; K tiles of 64 keys.
// K [b][s][d] and V^T [b][d][s] are both [n][k] K-major for the B operand.
// Writes fp16 output into a2 cols [0, 2048).
// ---------------------------------------------------------------------------
#define FROWB 144     // smem row stride bytes (64 halves + 8 pad)

__global__ __launch_bounds__(128) void fmha_kernel(
        const __half* __restrict__ q16, const __half* __restrict__ k16,
        const __half* __restrict__ vT, __half* __restrict__ a2) {
    __shared__ __half sQ[64 * 72];
    __shared__ __half sK[2][64 * 72];
    __shared__ __half sV[2][64 * 72];

    int tid = threadIdx.x;
    int w = tid >> 5, lane = tid & 31;
    int g = lane >> 2, t = lane & 3;
    int qt = (int)gridDim.x - 1 - (int)blockIdx.x;   // heavy tiles first
    int head = blockIdx.y;
    int b = blockIdx.z;

    const __half* gQ = q16 + ((size_t)(b * NHEAD + head) * SEQ + qt * 64) * DHEAD;
    const __half* gK = k16 + (size_t)b * SEQ * DHEAD;
    const __half* gV = vT + (size_t)b * DHEAD * SEQ;

    uint32_t sqa = smem_u32(sQ);
    uint32_t ska[2] = {smem_u32(sK[0]), smem_u32(sK[1])};
    uint32_t sva[2] = {smem_u32(sV[0]), smem_u32(sV[1])};

    auto load_kv = [&](int kt2, int buf2) {
        #pragma unroll
        for (int i = 0; i < 4; i++) {
            int idx = tid + i * 128;
            int r = idx >> 3, c = idx & 7;
            uint32_t so = (uint32_t)(r * FROWB + c * 16);
            CP_ASYNC16(ska[buf2] + so, (const void*)(gK + (size_t)(kt2 * 64 + r) * DHEAD + c * 8));
            CP_ASYNC16(sva[buf2] + so, (const void*)(gV + (size_t)r * SEQ + kt2 * 64 + c * 8));
        }
    };

    // prologue: Q + K0/V0
    #pragma unroll
    for (int i = 0; i < 4; i++) {
        int idx = tid + i * 128;
        int r = idx >> 3, c = idx & 7;
        uint32_t so = (uint32_t)(r * FROWB + c * 16);
        CP_ASYNC16(sqa + so, (const void*)(gQ + (size_t)r * DHEAD + c * 8));
    }
    load_kv(0, 0);
    CP_COMMIT();
    CP_WAIT(0);
    __syncthreads();

    // Q A-fragments (once)
    uint32_t aBase = (uint32_t)((w * 16 + (lane & 15)) * FROWB + (lane >> 4) * 16);
    uint32_t qa[4][4];
    #pragma unroll
    for (int ks = 0; ks < 4; ks++)
        LDSM_X4(qa[ks][0], qa[ks][1], qa[ks][2], qa[ks][3], sqa + aBase + ks * 32);

    uint32_t bBase = (uint32_t)((lane & 15) * FROWB + (lane >> 4) * 16);

    float o[8][4];
    #pragma unroll
    for (int n = 0; n < 8; n++)
        #pragma unroll
        for (int j = 0; j < 4; j++) o[n][j] = 0.0f;
    float m0 = -1e30f, m1 = -1e30f, l0 = 0.0f, l1 = 0.0f;

    for (int kt = 0; kt <= qt; kt++) {
        int buf = kt & 1;
        if (kt > 0) { CP_WAIT(0); __syncthreads(); }
        if (kt + 1 <= qt) { load_kv(kt + 1, buf ^ 1); CP_COMMIT(); }

        // S = Q K^T
        float s[8][4];
        #pragma unroll
        for (int n = 0; n < 8; n++)
            #pragma unroll
            for (int j = 0; j < 4; j++) s[n][j] = 0.0f;
        #pragma unroll
        for (int ng = 0; ng < 4; ng++) {
            #pragma unroll
            for (int ks = 0; ks < 4; ks++) {
                uint32_t bf[4];
                LDSM_X4(bf[0], bf[1], bf[2], bf[3],
                        ska[buf] + (uint32_t)(ng * 16 * FROWB) + bBase + ks * 32);
                MMA16816(s[2*ng],   qa[ks][0], qa[ks][1], qa[ks][2], qa[ks][3], bf[0], bf[2]);
                MMA16816(s[2*ng+1], qa[ks][0], qa[ks][1], qa[ks][2], qa[ks][3], bf[1], bf[3]);
            }
        }

        // causal mask on diagonal tile
        if (kt == qt) {
            int r0 = w * 16 + g;
            #pragma unroll
            for (int n = 0; n < 8; n++) {
                int c0 = n * 8 + 2 * t;
                if (c0 > r0)         s[n][0] = -1e30f;
                if (c0 + 1 > r0)     s[n][1] = -1e30f;
                if (c0 > r0 + 8)     s[n][2] = -1e30f;
                if (c0 + 1 > r0 + 8) s[n][3] = -1e30f;
            }
        }

        // online softmax (log2 domain)
        float tm0 = -1e30f, tm1 = -1e30f;
        #pragma unroll
        for (int n = 0; n < 8; n++) {
            tm0 = fmaxf(tm0, fmaxf(s[n][0], s[n][1]));
            tm1 = fmaxf(tm1, fmaxf(s[n][2], s[n][3]));
        }
        tm0 = fmaxf(tm0, __shfl_xor_sync(0xffffffffu, tm0, 1));
        tm0 = fmaxf(tm0, __shfl_xor_sync(0xffffffffu, tm0, 2));
        tm1 = fmaxf(tm1, __shfl_xor_sync(0xffffffffu, tm1, 1));
        tm1 = fmaxf(tm1, __shfl_xor_sync(0xffffffffu, tm1, 2));
        float mn0 = fmaxf(m0, tm0), mn1 = fmaxf(m1, tm1);
        float sc0 = exp2_poly(m0 - mn0), sc1 = exp2_poly(m1 - mn1);
        m0 = mn0; m1 = mn1;
        float ts0 = 0.0f, ts1 = 0.0f;
        #pragma unroll
        for (int n = 0; n < 8; n++) {
            s[n][0] = exp2_poly(s[n][0] - mn0);
            s[n][1] = exp2_poly(s[n][1] - mn0);
            s[n][2] = exp2_poly(s[n][2] - mn1);
            s[n][3] = exp2_poly(s[n][3] - mn1);
            ts0 += s[n][0] + s[n][1];
            ts1 += s[n][2] + s[n][3];
        }
        ts0 += __shfl_xor_sync(0xffffffffu, ts0, 1);
        ts0 += __shfl_xor_sync(0xffffffffu, ts0, 2);
        ts1 += __shfl_xor_sync(0xffffffffu, ts1, 1);
        ts1 += __shfl_xor_sync(0xffffffffu, ts1, 2);
        l0 = l0 * sc0 + ts0;
        l1 = l1 * sc1 + ts1;
        #pragma unroll
        for (int n = 0; n < 8; n++) {
            o[n][0] *= sc0; o[n][1] *= sc0;
            o[n][2] *= sc1; o[n][3] *= sc1;
        }

        // P fragments
        uint32_t pa[4][4];
        #pragma unroll
        for (int kk = 0; kk < 4; kk++) {
            pa[kk][0] = packh2(s[2*kk][0],   s[2*kk][1]);
            pa[kk][1] = packh2(s[2*kk][2],   s[2*kk][3]);
            pa[kk][2] = packh2(s[2*kk+1][0], s[2*kk+1][1]);
            pa[kk][3] = packh2(s[2*kk+1][2], s[2*kk+1][3]);
        }

        // O += P V
        #pragma unroll
        for (int ng = 0; ng < 4; ng++) {
            #pragma unroll
            for (int kk = 0; kk < 4; kk++) {
                uint32_t bf[4];
                LDSM_X4(bf[0], bf[1], bf[2], bf[3],
                        sva[buf] + (uint32_t)(ng * 16 * FROWB) + bBase + kk * 32);
                MMA16816(o[2*ng],   pa[kk][0], pa[kk][1], pa[kk][2], pa[kk][3], bf[0], bf[2]);
                MMA16816(o[2*ng+1], pa[kk][0], pa[kk][1], pa[kk][2], pa[kk][3], bf[1], bf[3]);
            }
        }
    }

    // write output (fp16 into a2)
    float inv0 = 1.0f / l0, inv1 = 1.0f / l1;
    int row0 = qt * 64 + w * 16 + g;
    size_t t0 = ((size_t)b * SEQ + row0) * OUTK + head * 64;
    size_t t1 = t0 + (size_t)8 * OUTK;
    #pragma unroll
    for (int n = 0; n < 8; n++) {
        int coff = n * 8 + 2 * t;
        *reinterpret_cast<__half2*>(a2 + t0 + coff) = h2(o[n][0] * inv0, o[n][1] * inv0);
        *reinterpret_cast<__half2*>(a2 + t1 + coff) = h2(o[n][2] * inv1, o[n][3] * inv1);
    }
}

// ---------------------------------------------------------------------------
// Kernel: convert ffn region of g_h into A2 cols [2048, 10240) as fp16
// ---------------------------------------------------------------------------
__global__ void ffn_split_kernel(const float* __restrict__ h,
                                 __half* __restrict__ a2) {
    size_t i = (size_t)blockIdx.x * blockDim.x + threadIdx.x;
    int m  = (int)(i >> 11);
    int j4 = (int)(i & 2047);
    float4 v = *reinterpret_cast<const float4*>(h + (size_t)m * HCOLS + 2176 + j4 * 4);
    size_t ob = (size_t)m * OUTK + 2048 + j4 * 4;
    __half2* ph = reinterpret_cast<__half2*>(a2 + ob);
    ph[0] = h2(v.x, v.y);
    ph[1] = h2(v.z, v.w);
}

// ---------------------------------------------------------------------------
extern "C" void kernel_launch(void* const* d_in, const int* in_sizes, int n_in,
                              void* d_out, int out_size) {
    const float* x     = (const float*)d_in[0];
    const float* W_in  = (const float*)d_in[1];
    const float* W_out = (const float*)d_in[2];
    const float* gamma = (const float*)d_in[3];
    const float* beta  = (const float*)d_in[4];
    float* out = (float*)d_out;

    float* xn;  cudaGetSymbolAddress((void**)&xn,  g_xn);
    float* h;   cudaGetSymbolAddress((void**)&h,   g_h);
    __half *a1, *w1, *a2, *w2, *q16, *k16, *vT;
    cudaGetSymbolAddress((void**)&a1,  g_a1);
    cudaGetSymbolAddress((void**)&w1,  g_w1);
    cudaGetSymbolAddress((void**)&a2,  g_a2);
    cudaGetSymbolAddress((void**)&w2,  g_w2);
    cudaGetSymbolAddress((void**)&q16, g_q16);
    cudaGetSymbolAddress((void**)&k16, g_k16);
    cudaGetSymbolAddress((void**)&vT,  g_vT);

    const int SMEM = NSTAGE * STAGEB;   // 81920 -> 2 CTAs/SM
    cudaFuncSetAttribute(gemm_mma<false>, cudaFuncAttributeMaxDynamicSharedMemorySize, SMEM);
    cudaFuncSetAttribute(gemm_mma<true>,  cudaFuncAttributeMaxDynamicSharedMemorySize, SMEM);

    ln_split_kernel<<<MTOK, 256>>>(x, gamma, beta, xn, a1);
    tsplit_kernel<<<dim3(HCOLS/32, DIM/32), dim3(32, 8)>>>(W_in, LDWIN, w1, DIM);
    tsplit_kernel<<<dim3(DIM/32, OUTK/32), dim3(32, 8)>>>(W_out, DIM, w2, OUTK);
    gemm_mma<false><<<dim3(MTOK/128, HCOLS/128), 256, SMEM>>>(
        a1, w1, h, DIM, HCOLS, nullptr);
    qkv_prep_kernel<<<MTOK, 128>>>(h, q16, k16, vT);
    fmha_kernel<<<dim3(SEQ/64, NHEAD, BATCH), 128>>>(q16, k16, vT, a2);
    ffn_split_kernel<<<(MTOK * 2048) / 256, 256>>>(h, a2);
    gemm_mma<true><<<dim3(MTOK/128, DIM/128), 256, SMEM>>>(
        a2, w2, out, OUTK, DIM, xn);
}